// round 4
// baseline (speedup 1.0000x reference)
#include <cuda_runtime.h>
#include <math.h>

#define NEXP    8
#define HDIM    4096
#define TOK     4
#define WARPS   16
#define THREADS 512
#define NTOK    16384            // 4 * 4096 tokens
#define NGROUP  (NTOK / TOK)     // 4096 warp-groups
#define H4      (HDIM / 4)       // 1024 float4 per row
#define KITERS  (H4 / 32)        // 32 k-iterations per group
#define NBUF    3

// One k-iteration: consume hbuf[S], then (optionally) prefetch iter i+NBUF
// into the same buffer. Weights loaded in two 4-expert phases to cap live regs.
template<int S, bool PF>
__device__ __forceinline__ void do_stage(int i, int lane,
                                         const float4* __restrict__ hs4,
                                         const float4* __restrict__ sw4,
                                         float4 (&hbuf)[NBUF][TOK],
                                         float (&acc)[TOK][NEXP])
{
    const int kk = i * 32 + lane;

    // phase 0: experts 0..3
    {
        float4 w[4];
        #pragma unroll
        for (int e = 0; e < 4; e++)
            w[e] = sw4[e * H4 + kk];
        #pragma unroll
        for (int t = 0; t < TOK; t++) {
            const float4 h = hbuf[S][t];
            #pragma unroll
            for (int e = 0; e < 4; e++) {
                acc[t][e] = fmaf(h.x, w[e].x, acc[t][e]);
                acc[t][e] = fmaf(h.y, w[e].y, acc[t][e]);
                acc[t][e] = fmaf(h.z, w[e].z, acc[t][e]);
                acc[t][e] = fmaf(h.w, w[e].w, acc[t][e]);
            }
        }
    }
    // phase 1: experts 4..7
    {
        float4 w[4];
        #pragma unroll
        for (int e = 0; e < 4; e++)
            w[e] = sw4[(e + 4) * H4 + kk];
        #pragma unroll
        for (int t = 0; t < TOK; t++) {
            const float4 h = hbuf[S][t];
            #pragma unroll
            for (int e = 0; e < 4; e++) {
                acc[t][e + 4] = fmaf(h.x, w[e].x, acc[t][e + 4]);
                acc[t][e + 4] = fmaf(h.y, w[e].y, acc[t][e + 4]);
                acc[t][e + 4] = fmaf(h.z, w[e].z, acc[t][e + 4]);
                acc[t][e + 4] = fmaf(h.w, w[e].w, acc[t][e + 4]);
            }
        }
    }
    // prefetch iter i+NBUF into the buffer we just finished reading
    if (PF) {
        const int kk3 = kk + NBUF * 32;
        #pragma unroll
        for (int t = 0; t < TOK; t++)
            hbuf[S][t] = __ldcs(&hs4[(size_t)t * H4 + kk3]);
    }
}

__global__ __launch_bounds__(THREADS, 1)
void moe_router_kernel(const float* __restrict__ hs,
                       const float* __restrict__ rw,
                       float* __restrict__ out)
{
    extern __shared__ float sw[];          // [NEXP][HDIM] = 128 KB
    float4* sw4 = reinterpret_cast<float4*>(sw);

    // Stage router weights into shared memory (coalesced, once per block)
    {
        const float4* rw4 = reinterpret_cast<const float4*>(rw);
        for (int i = threadIdx.x; i < NEXP * H4; i += THREADS)
            sw4[i] = rw4[i];
    }
    __syncthreads();

    const int lane = threadIdx.x & 31;
    const int wid  = threadIdx.x >> 5;
    // Interleaved mapping: spreads multi-group warps across all SMs
    const int gwarp = wid * gridDim.x + blockIdx.x;
    const int nwarp = gridDim.x * WARPS;

    float* out_w = out;                     // [NTOK, 2] top-k weights
    float* out_i = out + (size_t)NTOK * 2;  // [NTOK, 2] indices (as float)
    float* out_l = out + (size_t)NTOK * 4;  // [NTOK, 8] raw logits

    for (int g = gwarp; g < NGROUP; g += nwarp) {
        const size_t t0 = (size_t)g * TOK;
        const float4* hs4 = reinterpret_cast<const float4*>(hs) + t0 * H4;

        float acc[TOK][NEXP];
        #pragma unroll
        for (int t = 0; t < TOK; t++)
            #pragma unroll
            for (int e = 0; e < NEXP; e++)
                acc[t][e] = 0.0f;

        // Prologue: fill the 3-stage pipeline (iters 0,1,2)
        float4 hbuf[NBUF][TOK];
        #pragma unroll
        for (int s = 0; s < NBUF; s++)
            #pragma unroll
            for (int t = 0; t < TOK; t++)
                hbuf[s][t] = __ldcs(&hs4[(size_t)t * H4 + s * 32 + lane]);

        // Main loop: 9 rotations of 3 stages (iters 0..26), prefetching 3..29
        #pragma unroll 1
        for (int i = 0; i < KITERS - 5; i += 3) {
            do_stage<0, true>(i,     lane, hs4, sw4, hbuf, acc);
            do_stage<1, true>(i + 1, lane, hs4, sw4, hbuf, acc);
            do_stage<2, true>(i + 2, lane, hs4, sw4, hbuf, acc);
        }
        // Tail: iters 27,28 (prefetch 30,31), then 29,30,31 compute-only
        do_stage<0, true >(KITERS - 5, lane, hs4, sw4, hbuf, acc);
        do_stage<1, true >(KITERS - 4, lane, hs4, sw4, hbuf, acc);
        do_stage<2, false>(KITERS - 3, lane, hs4, sw4, hbuf, acc);
        do_stage<0, false>(KITERS - 2, lane, hs4, sw4, hbuf, acc);
        do_stage<1, false>(KITERS - 1, lane, hs4, sw4, hbuf, acc);

        // Butterfly reduction: every lane ends with all TOK*NEXP sums
        #pragma unroll
        for (int off = 16; off > 0; off >>= 1) {
            #pragma unroll
            for (int t = 0; t < TOK; t++)
                #pragma unroll
                for (int e = 0; e < NEXP; e++)
                    acc[t][e] += __shfl_xor_sync(0xffffffffu, acc[t][e], off);
        }

        // Lanes 0..TOK-1: one token each — top-2 + renorm + writes
        if (lane < TOK) {
            float l[NEXP];
            #pragma unroll
            for (int t = 0; t < TOK; t++) {
                if (lane == t) {
                    #pragma unroll
                    for (int e = 0; e < NEXP; e++) l[e] = acc[t][e];
                }
            }

            const size_t tok = t0 + lane;

            // argmax (ties -> lowest index, matching jax.lax.top_k)
            int   i1 = 0; float v1 = l[0];
            #pragma unroll
            for (int e = 1; e < NEXP; e++)
                if (l[e] > v1) { v1 = l[e]; i1 = e; }
            int   i2 = -1; float v2 = -INFINITY;
            #pragma unroll
            for (int e = 0; e < NEXP; e++)
                if (e != i1 && l[e] > v2) { v2 = l[e]; i2 = e; }

            // renormalized top-2 softmax weights
            const float e2 = __expf(v2 - v1);
            const float r  = 1.0f / (1.0f + e2);

            out_w[tok * 2 + 0] = r;
            out_w[tok * 2 + 1] = e2 * r;
            out_i[tok * 2 + 0] = (float)i1;
            out_i[tok * 2 + 1] = (float)i2;
            #pragma unroll
            for (int e = 0; e < NEXP; e++)
                out_l[tok * NEXP + e] = l[e];
        }
    }
}

extern "C" void kernel_launch(void* const* d_in, const int* in_sizes, int n_in,
                              void* d_out, int out_size)
{
    const float* hs = (const float*)d_in[0];   // hidden_states [4,4096,4096] f32
    const float* rw = (const float*)d_in[1];   // router_weight [8,4096] f32
    float* out = (float*)d_out;

    (void)in_sizes; (void)n_in; (void)out_size;

    cudaFuncSetAttribute(moe_router_kernel,
                         cudaFuncAttributeMaxDynamicSharedMemorySize,
                         NEXP * HDIM * (int)sizeof(float));

    moe_router_kernel<<<152, THREADS, NEXP * HDIM * sizeof(float)>>>(hs, rw, out);
}

// round 5
// speedup vs baseline: 1.0043x; 1.0043x over previous
#include <cuda_runtime.h>
#include <math.h>

#define NEXP    8
#define HDIM    4096
#define WARPS   16
#define THREADS 512
#define BLOCKS  152
#define NTOK    16384            // 4 * 4096 tokens
#define NWARP   (BLOCKS * WARPS) // 2432
#define H4      (HDIM / 4)       // 1024 float4 per row
#define KITERS  (H4 / 32)        // 32 k-iterations per group
// token split: first RBIG warps get 7 tokens, rest get 6
#define TOK_BIG   7
#define TOK_SMALL 6
#define RBIG      (NTOK - TOK_SMALL * NWARP)   // 1792

// Process one group of TOKN consecutive tokens (R2-proven inner structure).
template<int TOKN>
__device__ __forceinline__ void process_group(size_t t0, int lane,
                                              const float4* __restrict__ hsb,
                                              const float4* __restrict__ sw4,
                                              float* __restrict__ out_w,
                                              float* __restrict__ out_i,
                                              float* __restrict__ out_l)
{
    const float4* hs4 = hsb + t0 * H4;

    float acc[TOKN][NEXP];
    #pragma unroll
    for (int t = 0; t < TOKN; t++)
        #pragma unroll
        for (int e = 0; e < NEXP; e++)
            acc[t][e] = 0.0f;

    // Double-buffered hidden loads
    float4 hbuf[2][TOKN];
    #pragma unroll
    for (int t = 0; t < TOKN; t++)
        hbuf[0][t] = __ldcs(&hs4[(size_t)t * H4 + lane]);

    #pragma unroll 4
    for (int i = 0; i < KITERS; i++) {
        const int cur = i & 1;

        if (i + 1 < KITERS) {
            const int kk2 = (i + 1) * 32 + lane;
            #pragma unroll
            for (int t = 0; t < TOKN; t++)
                hbuf[cur ^ 1][t] = __ldcs(&hs4[(size_t)t * H4 + kk2]);
        }

        const int kk = i * 32 + lane;
        float4 w[NEXP];
        #pragma unroll
        for (int e = 0; e < NEXP; e++)
            w[e] = sw4[e * H4 + kk];

        #pragma unroll
        for (int t = 0; t < TOKN; t++) {
            const float4 h = hbuf[cur][t];
            #pragma unroll
            for (int e = 0; e < NEXP; e++) {
                acc[t][e] = fmaf(h.x, w[e].x, acc[t][e]);
                acc[t][e] = fmaf(h.y, w[e].y, acc[t][e]);
                acc[t][e] = fmaf(h.z, w[e].z, acc[t][e]);
                acc[t][e] = fmaf(h.w, w[e].w, acc[t][e]);
            }
        }
    }

    // Butterfly reduction: every lane ends with all TOKN*NEXP sums
    #pragma unroll
    for (int off = 16; off > 0; off >>= 1) {
        #pragma unroll
        for (int t = 0; t < TOKN; t++)
            #pragma unroll
            for (int e = 0; e < NEXP; e++)
                acc[t][e] += __shfl_xor_sync(0xffffffffu, acc[t][e], off);
    }

    // Lanes 0..TOKN-1: one token each — top-2 + renorm + writes
    if (lane < TOKN) {
        float l[NEXP];
        #pragma unroll
        for (int t = 0; t < TOKN; t++) {
            if (lane == t) {
                #pragma unroll
                for (int e = 0; e < NEXP; e++) l[e] = acc[t][e];
            }
        }

        const size_t tok = t0 + lane;

        // argmax (ties -> lowest index, matching jax.lax.top_k)
        int   i1 = 0; float v1 = l[0];
        #pragma unroll
        for (int e = 1; e < NEXP; e++)
            if (l[e] > v1) { v1 = l[e]; i1 = e; }
        int   i2 = -1; float v2 = -INFINITY;
        #pragma unroll
        for (int e = 0; e < NEXP; e++)
            if (e != i1 && l[e] > v2) { v2 = l[e]; i2 = e; }

        // renormalized top-2 softmax weights
        const float e2 = __expf(v2 - v1);
        const float r  = 1.0f / (1.0f + e2);

        out_w[tok * 2 + 0] = r;
        out_w[tok * 2 + 1] = e2 * r;
        out_i[tok * 2 + 0] = (float)i1;
        out_i[tok * 2 + 1] = (float)i2;
        #pragma unroll
        for (int e = 0; e < NEXP; e++)
            out_l[tok * NEXP + e] = l[e];
    }
}

__global__ __launch_bounds__(THREADS, 1)
void moe_router_kernel(const float* __restrict__ hs,
                       const float* __restrict__ rw,
                       float* __restrict__ out)
{
    extern __shared__ float sw[];          // [NEXP][HDIM] = 128 KB
    float4* sw4 = reinterpret_cast<float4*>(sw);

    // Stage router weights into shared memory (coalesced, once per block)
    {
        const float4* rw4 = reinterpret_cast<const float4*>(rw);
        for (int i = threadIdx.x; i < NEXP * H4; i += THREADS)
            sw4[i] = rw4[i];
    }
    __syncthreads();

    const int lane = threadIdx.x & 31;
    const int wid  = threadIdx.x >> 5;
    // Interleaved mapping: spreads the 7-token warps across all SMs
    const int gwarp = wid * gridDim.x + blockIdx.x;

    float* out_w = out;                     // [NTOK, 2] top-k weights
    float* out_i = out + (size_t)NTOK * 2;  // [NTOK, 2] indices (as float)
    float* out_l = out + (size_t)NTOK * 4;  // [NTOK, 8] raw logits

    const float4* hsb = reinterpret_cast<const float4*>(hs);

    // Exact token partition: warps [0, RBIG) own 7 tokens, rest own 6.
    if (gwarp < RBIG) {
        const size_t base = (size_t)gwarp * TOK_BIG;
        process_group<4>(base,     lane, hsb, sw4, out_w, out_i, out_l);
        process_group<3>(base + 4, lane, hsb, sw4, out_w, out_i, out_l);
    } else {
        const size_t base = (size_t)RBIG * TOK_BIG
                          + (size_t)(gwarp - RBIG) * TOK_SMALL;
        process_group<3>(base,     lane, hsb, sw4, out_w, out_i, out_l);
        process_group<3>(base + 3, lane, hsb, sw4, out_w, out_i, out_l);
    }
}

extern "C" void kernel_launch(void* const* d_in, const int* in_sizes, int n_in,
                              void* d_out, int out_size)
{
    const float* hs = (const float*)d_in[0];   // hidden_states [4,4096,4096] f32
    const float* rw = (const float*)d_in[1];   // router_weight [8,4096] f32
    float* out = (float*)d_out;

    (void)in_sizes; (void)n_in; (void)out_size;

    cudaFuncSetAttribute(moe_router_kernel,
                         cudaFuncAttributeMaxDynamicSharedMemorySize,
                         NEXP * HDIM * (int)sizeof(float));

    moe_router_kernel<<<BLOCKS, THREADS, NEXP * HDIM * sizeof(float)>>>(hs, rw, out);
}

// round 6
// speedup vs baseline: 1.0457x; 1.0412x over previous
#include <cuda_runtime.h>
#include <math.h>

#define NEXP    8
#define HDIM    4096
#define TOK     4
#define WARPS   16
#define THREADS 512
#define NTOK    16384            // 4 * 4096 tokens
#define NGROUP  (NTOK / TOK)     // 4096 warp-groups
#define H4      (HDIM / 4)       // 1024 float4 per row
#define KITERS  (H4 / 32)        // 32 k-iterations per group

__global__ __launch_bounds__(THREADS, 1)
void moe_router_kernel(const float* __restrict__ hs,
                       const float* __restrict__ rw,
                       float* __restrict__ out)
{
    extern __shared__ float sw[];          // [NEXP][HDIM] = 128 KB
    float4* sw4 = reinterpret_cast<float4*>(sw);

    // Stage router weights into shared memory (coalesced, once per block)
    {
        const float4* rw4 = reinterpret_cast<const float4*>(rw);
        #pragma unroll
        for (int i = threadIdx.x; i < NEXP * H4; i += THREADS)
            sw4[i] = rw4[i];
    }
    __syncthreads();

    const int lane  = threadIdx.x & 31;
    const int wid   = threadIdx.x >> 5;
    const int gwarp = blockIdx.x * WARPS + wid;
    const int nwarp = gridDim.x * WARPS;

    float* out_w = out;                     // [NTOK, 2] top-k weights
    float* out_i = out + (size_t)NTOK * 2;  // [NTOK, 2] indices (as float)
    float* out_l = out + (size_t)NTOK * 4;  // [NTOK, 8] raw logits

    for (int g = gwarp; g < NGROUP; g += nwarp) {
        const size_t t0 = (size_t)g * TOK;
        const float4* hs4 = reinterpret_cast<const float4*>(hs) + t0 * H4;

        // v[t*8+e] = partial logit for token t, expert e (this lane's k-slice)
        float v[TOK * NEXP];
        #pragma unroll
        for (int x = 0; x < TOK * NEXP; x++) v[x] = 0.0f;

        // Double-buffered hidden loads (R2-proven mainloop)
        float4 hbuf[2][TOK];
        #pragma unroll
        for (int t = 0; t < TOK; t++)
            hbuf[0][t] = __ldcs(&hs4[(size_t)t * H4 + lane]);

        #pragma unroll 4
        for (int i = 0; i < KITERS; i++) {
            const int cur = i & 1;

            if (i + 1 < KITERS) {
                const int kk2 = (i + 1) * 32 + lane;
                #pragma unroll
                for (int t = 0; t < TOK; t++)
                    hbuf[cur ^ 1][t] = __ldcs(&hs4[(size_t)t * H4 + kk2]);
            }

            const int kk = i * 32 + lane;
            float4 w[NEXP];
            #pragma unroll
            for (int e = 0; e < NEXP; e++)
                w[e] = sw4[e * H4 + kk];

            #pragma unroll
            for (int t = 0; t < TOK; t++) {
                const float4 h = hbuf[cur][t];
                #pragma unroll
                for (int e = 0; e < NEXP; e++) {
                    v[t * NEXP + e] = fmaf(h.x, w[e].x, v[t * NEXP + e]);
                    v[t * NEXP + e] = fmaf(h.y, w[e].y, v[t * NEXP + e]);
                    v[t * NEXP + e] = fmaf(h.z, w[e].z, v[t * NEXP + e]);
                    v[t * NEXP + e] = fmaf(h.w, w[e].w, v[t * NEXP + e]);
                }
            }
        }

        // Tree-exchange reduction: 31 SHFL total (vs 160 for full butterfly).
        // After this, lane L holds the complete sum for value index L = t*8+e.
        #pragma unroll
        for (int o = 16; o >= 1; o >>= 1) {
            const bool up = (lane & o) != 0;
            #pragma unroll
            for (int j = 0; j < o; j++) {
                const float give = up ? v[j] : v[j + o];
                const float keep = up ? v[j + o] : v[j];
                const float recv = __shfl_xor_sync(0xffffffffu, give, o);
                v[j] = keep + recv;
            }
        }

        const float logit = v[0];       // logit[token = lane>>3][expert = lane&7]
        const int   sub   = lane & 7;

        // Coalesced logit store: 32 consecutive floats per warp
        out_l[t0 * NEXP + lane] = logit;

        // Top-1 within each 8-lane token group (ties -> lowest expert index)
        float bv = logit; int bi = sub;
        #pragma unroll
        for (int o = 4; o >= 1; o >>= 1) {
            const float ov = __shfl_xor_sync(0xffffffffu, bv, o);
            const int   oi = __shfl_xor_sync(0xffffffffu, bi, o);
            if (ov > bv || (ov == bv && oi < bi)) { bv = ov; bi = oi; }
        }
        // Top-2: exclude the winner, reduce again
        float sv = (sub == bi) ? -INFINITY : logit; int si = sub;
        #pragma unroll
        for (int o = 4; o >= 1; o >>= 1) {
            const float ov = __shfl_xor_sync(0xffffffffu, sv, o);
            const int   oi = __shfl_xor_sync(0xffffffffu, si, o);
            if (ov > sv || (ov == sv && oi < si)) { sv = ov; si = oi; }
        }

        if (sub == 0) {
            const size_t tok = t0 + (lane >> 3);
            // renormalized top-2 softmax weights
            const float e2 = __expf(sv - bv);
            const float r  = 1.0f / (1.0f + e2);
            out_w[tok * 2 + 0] = r;
            out_w[tok * 2 + 1] = e2 * r;
            out_i[tok * 2 + 0] = (float)bi;
            out_i[tok * 2 + 1] = (float)si;
        }
    }
}

extern "C" void kernel_launch(void* const* d_in, const int* in_sizes, int n_in,
                              void* d_out, int out_size)
{
    const float* hs = (const float*)d_in[0];   // hidden_states [4,4096,4096] f32
    const float* rw = (const float*)d_in[1];   // router_weight [8,4096] f32
    float* out = (float*)d_out;

    (void)in_sizes; (void)n_in; (void)out_size;

    cudaFuncSetAttribute(moe_router_kernel,
                         cudaFuncAttributeMaxDynamicSharedMemorySize,
                         NEXP * HDIM * (int)sizeof(float));

    moe_router_kernel<<<152, THREADS, NEXP * HDIM * sizeof(float)>>>(hs, rw, out);
}